// round 16
// baseline (speedup 1.0000x reference)
#include <cuda_runtime.h>
#include <cuda_bf16.h>
#include <cstdint>

// ---------------- problem shape ----------------
#define B_DIM 16384
#define F_DIM 2048
#define C_DIM 1000
#define C_PAD 1024

// ---------------- GEMM tiling ----------------
#define BM 64
#define BN 128
#define KT 64                  // K elems per stage (64 bf16 = 128B rows, SW128)
#define NKT (F_DIM / KT)       // 32
#define STAGES 3
#define A_BYTES (BM * 128)     // 8 KB
#define STAGE_BYTES (BM * 128 + BN * 128)   // 24 KB
#define NTHREADS 128           // 4 warps, warp grid 1x4, warp tile 64x32 (unchanged)

// ---------------- scratch (device globals) ----------------
__device__ __nv_bfloat16 g_A[(size_t)B_DIM * F_DIM];
__device__ __nv_bfloat16 g_P[(size_t)C_PAD * F_DIM];
__device__ float g_fsq[B_DIM];
__device__ float g_psq[C_PAD];

// ---------------- helpers ----------------
__device__ __forceinline__ unsigned smem_u32(const void* p) {
    return (unsigned)__cvta_generic_to_shared(p);
}
__device__ __forceinline__ void cp_async16(unsigned smem_dst, const void* gmem_src) {
    asm volatile("cp.async.cg.shared.global [%0], [%1], 16;\n" :: "r"(smem_dst), "l"(gmem_src));
}
__device__ __forceinline__ void cp_commit() {
    asm volatile("cp.async.commit_group;\n" ::: "memory");
}
__device__ __forceinline__ void cp_wait1() {          // keep <= STAGES-2 groups pending
    asm volatile("cp.async.wait_group 1;\n" ::: "memory");
}
#define SW128(off) ((off) ^ (((off) >> 3) & 0x70))

__device__ __forceinline__ void ldmatrix_x4(unsigned& r0, unsigned& r1,
                                            unsigned& r2, unsigned& r3, unsigned addr) {
    asm volatile("ldmatrix.sync.aligned.m8n8.x4.shared.b16 {%0,%1,%2,%3}, [%4];"
                 : "=r"(r0), "=r"(r1), "=r"(r2), "=r"(r3) : "r"(addr));
}
__device__ __forceinline__ void mma16816(float* d, const unsigned* a, const unsigned* b) {
    asm volatile("mma.sync.aligned.m16n8k16.row.col.f32.bf16.bf16.f32 "
                 "{%0,%1,%2,%3}, {%4,%5,%6,%7}, {%8,%9}, {%0,%1,%2,%3};"
                 : "+f"(d[0]), "+f"(d[1]), "+f"(d[2]), "+f"(d[3])
                 : "r"(a[0]), "r"(a[1]), "r"(a[2]), "r"(a[3]), "r"(b[0]), "r"(b[1]));
}

// ---------------- merged prep: fp32 -> bf16 + exact row sum-of-squares ----
__global__ void prep_all(const float* __restrict__ features,
                         const float* __restrict__ prototypes) {
    const int blk = blockIdx.x;
    const int tid = threadIdx.x;
    const bool isF = (blk < B_DIM);
    const int row = isF ? blk : (blk - B_DIM);

    __nv_bfloat162* d2 = reinterpret_cast<__nv_bfloat162*>(
        (isF ? g_A + (size_t)row * F_DIM : g_P + (size_t)row * F_DIM));

    if (!isF && row >= C_DIM) {   // zero-pad prototype rows
        __nv_bfloat162 z = __floats2bfloat162_rn(0.f, 0.f);
        for (int i = tid; i < F_DIM / 2; i += 256) d2[i] = z;
        if (tid == 0) g_psq[row] = 0.f;
        return;
    }

    const float4* s4 = reinterpret_cast<const float4*>(
        (isF ? features : prototypes) + (size_t)row * F_DIM);
    float s = 0.f;
    #pragma unroll
    for (int i = tid; i < F_DIM / 4; i += 256) {
        float4 v = __ldcs(s4 + i);
        s += v.x * v.x + v.y * v.y + v.z * v.z + v.w * v.w;
        d2[i * 2 + 0] = __floats2bfloat162_rn(v.x, v.y);
        d2[i * 2 + 1] = __floats2bfloat162_rn(v.z, v.w);
    }
    #pragma unroll
    for (int o = 16; o; o >>= 1) s += __shfl_xor_sync(0xffffffffu, s, o);
    __shared__ float red[8];
    if ((tid & 31) == 0) red[tid >> 5] = s;
    __syncthreads();
    if (tid == 0) {
        float t = 0.f;
        #pragma unroll
        for (int i = 0; i < 8; i++) t += red[i];
        if (isF) g_fsq[row] = t; else g_psq[row] = t;
    }
}

// ---------------- HMMA GEMM + fused epilogue ----------------
extern __shared__ char smem_raw[];

__device__ __forceinline__ void issue_loads(const __nv_bfloat16* gA, const __nv_bfloat16* gB,
                                            unsigned sbase, int s, int kt, int tid) {
    unsigned base = sbase + s * STAGE_BYTES;
    const __nv_bfloat16* srcA = gA + kt * KT;
    #pragma unroll
    for (int i = 0; i < 4; i++) {
        int c = i * NTHREADS + tid;     // 0..511 : row(64) x 16B-chunk(8)
        int row = c >> 3, col = c & 7;
        cp_async16(base + SW128(row * 128 + col * 16), srcA + (size_t)row * F_DIM + col * 8);
    }
    unsigned baseB = base + A_BYTES;
    const __nv_bfloat16* srcB = gB + kt * KT;
    #pragma unroll
    for (int i = 0; i < 8; i++) {
        int c = i * NTHREADS + tid;     // 0..1023 : row(128) x 16B-chunk(8)
        int row = c >> 3, col = c & 7;
        cp_async16(baseB + SW128(row * 128 + col * 16), srcB + (size_t)row * F_DIM + col * 8);
    }
}

__global__ void __launch_bounds__(NTHREADS, 3)
gemm_dist_hmma(float* __restrict__ out) {
    const int tid = threadIdx.x;
    const int wid = tid >> 5;
    const int lid = tid & 31;
    const int bn = blockIdx.x;     // 0..7  (fastest -> L2 reuse of A across bn)
    const int bm = blockIdx.y;     // 0..255

    const int wn0 = wid * 32;      // warp N origin (4 warps in N); warp M origin = 0

    unsigned sb = smem_u32(smem_raw);

    const __nv_bfloat16* gA = g_A + (size_t)(bm * BM) * F_DIM;
    const __nv_bfloat16* gB = g_P + (size_t)(bn * BN) * F_DIM;

    float acc[4][4][4];
    #pragma unroll
    for (int i = 0; i < 4; i++)
        #pragma unroll
        for (int j = 0; j < 4; j++)
            #pragma unroll
            for (int k = 0; k < 4; k++) acc[i][j][k] = 0.f;

    // ldmatrix row-bases; per-ks chunk offsets recomputed via XOR (swizzle)
    const int m_sw = (lid & 7);            // swizzle XOR key (row&7 == lid&7 here)
    const int hA = lid >> 4;               // A chunk low bit
    const int hB = (lid >> 3) & 1;         // B chunk low bit
    unsigned rbaseA[4], rbaseB[2];
    #pragma unroll
    for (int i = 0; i < 4; i++)
        rbaseA[i] = sb + (i * 16 + (lid & 15)) * 128;
    #pragma unroll
    for (int j = 0; j < 2; j++)
        rbaseB[j] = sb + A_BYTES + (wn0 + j * 16 + (lid & 7) + ((lid >> 4) << 3)) * 128;

    // prologue: fill STAGES-1 stages
    #pragma unroll
    for (int s = 0; s < STAGES - 1; s++) {
        issue_loads(gA, gB, sb, s, s, tid);
        cp_commit();
    }

    #pragma unroll 1
    for (int kt = 0; kt < NKT; kt++) {
        const int rs = kt % STAGES;                      // read stage
        const unsigned soff = rs * STAGE_BYTES;
        cp_wait1();
        __syncthreads();   // read-stage visible; write-stage fully consumed

        // produce first: overlap crossbar-writes with tensor work below
        const int wkt = kt + STAGES - 1;
        if (wkt < NKT) issue_loads(gA, gB, sb, wkt % STAGES, wkt, tid);
        cp_commit();

        #pragma unroll
        for (int ks = 0; ks < 4; ks++) {
            const unsigned cA = (unsigned)(((ks * 2 + hA) ^ m_sw) << 4) + soff;
            const unsigned cB = (unsigned)(((ks * 2 + hB) ^ m_sw) << 4) + soff;
            unsigned a[4][4];
            #pragma unroll
            for (int i = 0; i < 4; i++)
                ldmatrix_x4(a[i][0], a[i][1], a[i][2], a[i][3], rbaseA[i] + cA);
            unsigned bf[4][2];
            #pragma unroll
            for (int j = 0; j < 2; j++) {
                unsigned t0, t1, t2, t3;
                ldmatrix_x4(t0, t1, t2, t3, rbaseB[j] + cB);
                bf[j * 2][0] = t0; bf[j * 2][1] = t1;
                bf[j * 2 + 1][0] = t2; bf[j * 2 + 1][1] = t3;
            }
            #pragma unroll
            for (int i = 0; i < 4; i++)
                #pragma unroll
                for (int j = 0; j < 4; j++)
                    mma16816(acc[i][j], a[i], bf[j]);
        }
    }

    // ---------------- fused epilogue straight from accumulators ----------------
    const int g  = lid >> 2;      // 0..7
    const int tg = lid & 3;       // 0..3
    const int grow = bm * BM + g;             // warp M origin is 0
    const int gcolw = bn * BN + wn0 + 2 * tg;

    // hoist the 8 column terms (per-thread invariant across i)
    float ps0v[4], ps1v[4];
    bool okv[4];
    #pragma unroll
    for (int j = 0; j < 4; j++) {
        int col = gcolw + j * 8;
        okv[j] = (col < C_DIM);
        ps0v[j] = okv[j] ? g_psq[col] : 0.f;
        ps1v[j] = okv[j] ? g_psq[col + 1] : 0.f;
    }

    #pragma unroll
    for (int i = 0; i < 4; i++) {
        int r0 = grow + i * 16;
        float fs0 = g_fsq[r0];
        float fs1 = g_fsq[r0 + 8];
        #pragma unroll
        for (int j = 0; j < 4; j++) {
            if (okv[j]) {
                int col = gcolw + j * 8;
                float2 v0, v1;
                v0.x = -sqrtf(fmaxf(fmaf(-2.f, acc[i][j][0], fs0 + ps0v[j]), 0.f));
                v0.y = -sqrtf(fmaxf(fmaf(-2.f, acc[i][j][1], fs0 + ps1v[j]), 0.f));
                v1.x = -sqrtf(fmaxf(fmaf(-2.f, acc[i][j][2], fs1 + ps0v[j]), 0.f));
                v1.y = -sqrtf(fmaxf(fmaf(-2.f, acc[i][j][3], fs1 + ps1v[j]), 0.f));
                *reinterpret_cast<float2*>(out + (size_t)r0 * C_DIM + col) = v0;
                *reinterpret_cast<float2*>(out + (size_t)(r0 + 8) * C_DIM + col) = v1;
            }
        }
    }
}

// ---------------- launch ----------------
extern "C" void kernel_launch(void* const* d_in, const int* in_sizes, int n_in,
                              void* d_out, int out_size) {
    const float* features   = (const float*)d_in[0];
    const float* prototypes = (const float*)d_in[1];
    float* out = (float*)d_out;

    const int SMEM_BYTES = STAGES * STAGE_BYTES;   // 73728 (x3 CTAs = 216K <= 228K)
    cudaFuncSetAttribute(gemm_dist_hmma,
                         cudaFuncAttributeMaxDynamicSharedMemorySize, SMEM_BYTES);

    prep_all<<<B_DIM + C_PAD, 256>>>(features, prototypes);

    dim3 grid(C_PAD / BN, B_DIM / BM);   // (8, 256) — bn fastest; 2048 tiles
    gemm_dist_hmma<<<grid, NTHREADS, SMEM_BYTES>>>(out);
}

// round 17
// speedup vs baseline: 1.0368x; 1.0368x over previous
#include <cuda_runtime.h>
#include <cuda_bf16.h>
#include <cstdint>

// ---------------- problem shape ----------------
#define B_DIM 16384
#define F_DIM 2048
#define C_DIM 1000
#define C_PAD 1024

// ---------------- GEMM tiling ----------------
#define BM 128
#define BN 128
#define KT 64                  // K elems per stage (64 bf16 = 128B rows, SW128)
#define NKT (F_DIM / KT)       // 32
#define STAGES 3
#define A_BYTES (BM * 128)     // 16 KB
#define STAGE_BYTES (BM * 128 + BN * 128)   // 32 KB

// ---------------- scratch (device globals) ----------------
__device__ __nv_bfloat16 g_A[(size_t)B_DIM * F_DIM];
__device__ __nv_bfloat16 g_P[(size_t)C_PAD * F_DIM];
__device__ float g_fsq[B_DIM];
__device__ float g_psq[C_PAD];

// ---------------- helpers ----------------
__device__ __forceinline__ unsigned smem_u32(const void* p) {
    return (unsigned)__cvta_generic_to_shared(p);
}
__device__ __forceinline__ void cp_async16(unsigned smem_dst, const void* gmem_src) {
    asm volatile("cp.async.cg.shared.global [%0], [%1], 16;\n" :: "r"(smem_dst), "l"(gmem_src));
}
__device__ __forceinline__ void cp_commit() {
    asm volatile("cp.async.commit_group;\n" ::: "memory");
}
__device__ __forceinline__ void cp_wait1() {          // keep <= STAGES-2 groups pending
    asm volatile("cp.async.wait_group 1;\n" ::: "memory");
}
#define SW128(off) ((off) ^ (((off) >> 3) & 0x70))

__device__ __forceinline__ void ldmatrix_x4(unsigned& r0, unsigned& r1,
                                            unsigned& r2, unsigned& r3, unsigned addr) {
    asm volatile("ldmatrix.sync.aligned.m8n8.x4.shared.b16 {%0,%1,%2,%3}, [%4];"
                 : "=r"(r0), "=r"(r1), "=r"(r2), "=r"(r3) : "r"(addr));
}
__device__ __forceinline__ void mma16816(float* d, const unsigned* a, const unsigned* b) {
    asm volatile("mma.sync.aligned.m16n8k16.row.col.f32.bf16.bf16.f32 "
                 "{%0,%1,%2,%3}, {%4,%5,%6,%7}, {%8,%9}, {%0,%1,%2,%3};"
                 : "+f"(d[0]), "+f"(d[1]), "+f"(d[2]), "+f"(d[3])
                 : "r"(a[0]), "r"(a[1]), "r"(a[2]), "r"(a[3]), "r"(b[0]), "r"(b[1]));
}

// ---------------- merged prep: fp32 -> bf16 + exact row sum-of-squares ----
__global__ void prep_all(const float* __restrict__ features,
                         const float* __restrict__ prototypes) {
    const int blk = blockIdx.x;
    const int tid = threadIdx.x;
    const bool isF = (blk < B_DIM);
    const int row = isF ? blk : (blk - B_DIM);

    __nv_bfloat162* d2 = reinterpret_cast<__nv_bfloat162*>(
        (isF ? g_A + (size_t)row * F_DIM : g_P + (size_t)row * F_DIM));

    if (!isF && row >= C_DIM) {   // zero-pad prototype rows
        __nv_bfloat162 z = __floats2bfloat162_rn(0.f, 0.f);
        for (int i = tid; i < F_DIM / 2; i += 256) d2[i] = z;
        if (tid == 0) g_psq[row] = 0.f;
        return;
    }

    const float4* s4 = reinterpret_cast<const float4*>(
        (isF ? features : prototypes) + (size_t)row * F_DIM);
    float s = 0.f;
    #pragma unroll
    for (int i = tid; i < F_DIM / 4; i += 256) {
        float4 v = __ldcs(s4 + i);
        s += v.x * v.x + v.y * v.y + v.z * v.z + v.w * v.w;
        d2[i * 2 + 0] = __floats2bfloat162_rn(v.x, v.y);
        d2[i * 2 + 1] = __floats2bfloat162_rn(v.z, v.w);
    }
    #pragma unroll
    for (int o = 16; o; o >>= 1) s += __shfl_xor_sync(0xffffffffu, s, o);
    __shared__ float red[8];
    if ((tid & 31) == 0) red[tid >> 5] = s;
    __syncthreads();
    if (tid == 0) {
        float t = 0.f;
        #pragma unroll
        for (int i = 0; i < 8; i++) t += red[i];
        if (isF) g_fsq[row] = t; else g_psq[row] = t;
    }
}

// ---------------- HMMA GEMM + fused epilogue ----------------
extern __shared__ char smem_raw[];

__device__ __forceinline__ void issue_loads(const __nv_bfloat16* gA, const __nv_bfloat16* gB,
                                            unsigned sbase, int s, int kt, int tid) {
    unsigned base = sbase + s * STAGE_BYTES;
    const __nv_bfloat16* srcA = gA + kt * KT;
    #pragma unroll
    for (int i = 0; i < 4; i++) {
        int c = i * 256 + tid;          // 0..1023 : row(128) x 16B-chunk(8)
        int row = c >> 3, col = c & 7;
        cp_async16(base + SW128(row * 128 + col * 16), srcA + (size_t)row * F_DIM + col * 8);
    }
    unsigned baseB = base + A_BYTES;
    const __nv_bfloat16* srcB = gB + kt * KT;
    #pragma unroll
    for (int i = 0; i < 4; i++) {
        int c = i * 256 + tid;
        int row = c >> 3, col = c & 7;
        cp_async16(baseB + SW128(row * 128 + col * 16), srcB + (size_t)row * F_DIM + col * 8);
    }
}

__global__ void __launch_bounds__(256, 2)
gemm_dist_hmma(float* __restrict__ out) {
    const int tid = threadIdx.x;
    const int wid = tid >> 5;
    const int lid = tid & 31;
    const int bn = blockIdx.x;     // 0..7  (fastest -> L2 reuse of A across bn)
    const int bm = blockIdx.y;     // 0..127

    const int wm0 = (wid >> 2) * 64;   // warp M origin (2 warps in M)
    const int wn0 = (wid & 3) * 32;    // warp N origin (4 warps in N)

    unsigned sb = smem_u32(smem_raw);

    const __nv_bfloat16* gA = g_A + (size_t)(bm * BM) * F_DIM;
    const __nv_bfloat16* gB = g_P + (size_t)(bn * BN) * F_DIM;

    float acc[4][4][4];
    #pragma unroll
    for (int i = 0; i < 4; i++)
        #pragma unroll
        for (int j = 0; j < 4; j++)
            #pragma unroll
            for (int k = 0; k < 4; k++) acc[i][j][k] = 0.f;

    // ldmatrix row-bases; per-ks chunk offsets recomputed via XOR (swizzle)
    const int m_sw = (lid & 7);            // swizzle XOR key (row&7 == lid&7 here)
    const int hA = lid >> 4;               // A chunk low bit
    const int hB = (lid >> 3) & 1;         // B chunk low bit
    unsigned rbaseA[4], rbaseB[2];
    #pragma unroll
    for (int i = 0; i < 4; i++)
        rbaseA[i] = sb + (wm0 + i * 16 + (lid & 15)) * 128;
    #pragma unroll
    for (int j = 0; j < 2; j++)
        rbaseB[j] = sb + A_BYTES + (wn0 + j * 16 + (lid & 7) + ((lid >> 4) << 3)) * 128;

    // prologue: fill STAGES-1 stages
    #pragma unroll
    for (int s = 0; s < STAGES - 1; s++) {
        issue_loads(gA, gB, sb, s, s, tid);
        cp_commit();
    }

    #pragma unroll 1
    for (int kt = 0; kt < NKT; kt++) {
        const int rs = kt % STAGES;                      // read stage
        const unsigned soff = rs * STAGE_BYTES;
        cp_wait1();
        __syncthreads();   // read-stage visible; write-stage fully consumed

        // produce first: overlap crossbar-writes with tensor work below
        const int wkt = kt + STAGES - 1;
        if (wkt < NKT) issue_loads(gA, gB, sb, wkt % STAGES, wkt, tid);
        cp_commit();

        #pragma unroll
        for (int ks = 0; ks < 4; ks++) {
            const unsigned cA = (unsigned)(((ks * 2 + hA) ^ m_sw) << 4) + soff;
            const unsigned cB = (unsigned)(((ks * 2 + hB) ^ m_sw) << 4) + soff;
            unsigned a[4][4];
            #pragma unroll
            for (int i = 0; i < 4; i++)
                ldmatrix_x4(a[i][0], a[i][1], a[i][2], a[i][3], rbaseA[i] + cA);
            unsigned bf[4][2];
            #pragma unroll
            for (int j = 0; j < 2; j++) {
                unsigned t0, t1, t2, t3;
                ldmatrix_x4(t0, t1, t2, t3, rbaseB[j] + cB);
                bf[j * 2][0] = t0; bf[j * 2][1] = t1;
                bf[j * 2 + 1][0] = t2; bf[j * 2 + 1][1] = t3;
            }
            #pragma unroll
            for (int i = 0; i < 4; i++)
                #pragma unroll
                for (int j = 0; j < 4; j++)
                    mma16816(acc[i][j], a[i], bf[j]);
        }
    }

    // ---------------- fused epilogue straight from accumulators ----------------
    const int g  = lid >> 2;      // 0..7
    const int tg = lid & 3;       // 0..3
    const int grow = bm * BM + wm0 + g;
    const int gcolw = bn * BN + wn0 + 2 * tg;

    // hoist the 8 column terms (per-thread invariant across i)
    float ps0v[4], ps1v[4];
    bool okv[4];
    #pragma unroll
    for (int j = 0; j < 4; j++) {
        int col = gcolw + j * 8;
        okv[j] = (col < C_DIM);
        ps0v[j] = okv[j] ? g_psq[col] : 0.f;
        ps1v[j] = okv[j] ? g_psq[col + 1] : 0.f;
    }

    #pragma unroll
    for (int i = 0; i < 4; i++) {
        int r0 = grow + i * 16;
        float fs0 = g_fsq[r0];
        float fs1 = g_fsq[r0 + 8];
        #pragma unroll
        for (int j = 0; j < 4; j++) {
            if (okv[j]) {
                int col = gcolw + j * 8;
                float2 v0, v1;
                v0.x = -sqrtf(fmaxf(fmaf(-2.f, acc[i][j][0], fs0 + ps0v[j]), 0.f));
                v0.y = -sqrtf(fmaxf(fmaf(-2.f, acc[i][j][1], fs0 + ps1v[j]), 0.f));
                v1.x = -sqrtf(fmaxf(fmaf(-2.f, acc[i][j][2], fs1 + ps0v[j]), 0.f));
                v1.y = -sqrtf(fmaxf(fmaf(-2.f, acc[i][j][3], fs1 + ps1v[j]), 0.f));
                // streaming stores: output is write-once, keep L2 for A/B tiles
                __stwt(reinterpret_cast<float2*>(out + (size_t)r0 * C_DIM + col), v0);
                __stwt(reinterpret_cast<float2*>(out + (size_t)(r0 + 8) * C_DIM + col), v1);
            }
        }
    }
}

// ---------------- launch ----------------
extern "C" void kernel_launch(void* const* d_in, const int* in_sizes, int n_in,
                              void* d_out, int out_size) {
    const float* features   = (const float*)d_in[0];
    const float* prototypes = (const float*)d_in[1];
    float* out = (float*)d_out;

    const int SMEM_BYTES = STAGES * STAGE_BYTES;   // 98304 (x2 CTAs = 192K <= 228K)
    cudaFuncSetAttribute(gemm_dist_hmma,
                         cudaFuncAttributeMaxDynamicSharedMemorySize, SMEM_BYTES);

    prep_all<<<B_DIM + C_PAD, 256>>>(features, prototypes);

    dim3 grid(C_PAD / BN, B_DIM / BM);   // (8, 128) — bn fastest
    gemm_dist_hmma<<<grid, 256, SMEM_BYTES>>>(out);
}